// round 4
// baseline (speedup 1.0000x reference)
#include <cuda_runtime.h>
#include <stdint.h>

#define D_IN   64
#define D_OUT  128
#define MAX_NODES 100000
#define MAX_EDGES 1600000

#define SCAN_CHUNK 4096           // elements per scan block (1024 thr * 4)
#define SCAN_BLOCKS ((MAX_NODES + 1 + SCAN_CHUNK - 1) / SCAN_CHUNK)   // 25

// Scratch (device globals; no allocs allowed)
__device__ int g_cnt[MAX_NODES + 1];
__device__ int g_off[MAX_NODES + 1];
__device__ int g_rank[MAX_EDGES];       // within-bucket rank from histogram
__device__ int g_esrc[MAX_EDGES];       // src ids sorted by dst bucket
__device__ int g_bsum[SCAN_BLOCKS];

// ---------------------------------------------------------------------------
// 1) zero counts
// ---------------------------------------------------------------------------
__global__ void zero_cnt_kernel(int nelem) {
    int i = blockIdx.x * blockDim.x + threadIdx.x;
    if (i < nelem) g_cnt[i] = 0;
}

// ---------------------------------------------------------------------------
// 2) histogram of dst; atomicAdd return value = rank within bucket (free)
// ---------------------------------------------------------------------------
__global__ void hist_kernel(const int* __restrict__ dst, int e) {
    int i = blockIdx.x * blockDim.x + threadIdx.x;
    if (i < e) {
        g_rank[i] = atomicAdd(&g_cnt[dst[i]], 1);
    }
}

// ---------------------------------------------------------------------------
// 3a) per-block exclusive scan (1024 threads x 4 elems)
// ---------------------------------------------------------------------------
__global__ __launch_bounds__(1024)
void scan1_kernel(int nelem) {
    __shared__ int s[1024];
    int t = threadIdx.x;
    int base = blockIdx.x * SCAN_CHUNK + t * 4;

    int v0 = (base + 0 < nelem) ? g_cnt[base + 0] : 0;
    int v1 = (base + 1 < nelem) ? g_cnt[base + 1] : 0;
    int v2 = (base + 2 < nelem) ? g_cnt[base + 2] : 0;
    int v3 = (base + 3 < nelem) ? g_cnt[base + 3] : 0;
    int tsum = v0 + v1 + v2 + v3;

    s[t] = tsum;
    __syncthreads();
    #pragma unroll
    for (int off = 1; off < 1024; off <<= 1) {
        int x = (t >= off) ? s[t - off] : 0;
        __syncthreads();
        if (t >= off) s[t] += x;
        __syncthreads();
    }
    int excl = s[t] - tsum;
    if (t == 1023) g_bsum[blockIdx.x] = s[1023];

    int run = excl;
    if (base + 0 < nelem) { g_off[base + 0] = run; } run += v0;
    if (base + 1 < nelem) { g_off[base + 1] = run; } run += v1;
    if (base + 2 < nelem) { g_off[base + 2] = run; } run += v2;
    if (base + 3 < nelem) { g_off[base + 3] = run; }
}

// 3b) exclusive scan of block sums — single warp shfl scan (nblocks<=32)
__global__ void scan2_kernel(int nblocks) {
    int lane = threadIdx.x;
    int v = (lane < nblocks) ? g_bsum[lane] : 0;
    int orig = v;
    #pragma unroll
    for (int off = 1; off < 32; off <<= 1) {
        int x = __shfl_up_sync(0xFFFFFFFFu, v, off);
        if (lane >= off) v += x;
    }
    if (lane < nblocks) g_bsum[lane] = v - orig;   // exclusive
}

// 3c) add block offsets
__global__ void scan3_kernel(int nelem) {
    int i = blockIdx.x * blockDim.x + threadIdx.x;
    if (i < nelem) {
        g_off[i] += g_bsum[i / SCAN_CHUNK];
    }
}

// ---------------------------------------------------------------------------
// 4) fill sorted src list — no atomics (rank precomputed by histogram)
// ---------------------------------------------------------------------------
__global__ void fill_kernel(const int* __restrict__ src,
                            const int* __restrict__ dst, int e) {
    int i = blockIdx.x * blockDim.x + threadIdx.x;
    if (i < e) {
        int p = g_off[dst[i]] + g_rank[i];
        g_esrc[p] = src[i];
    }
}

// ---------------------------------------------------------------------------
// 5) FUSED segment-reduce + GEMM.
//    Block = 256 threads, 16 nodes.
//    Phase A: half-warp (16 lanes x float4) per node gathers+sums into smem.
//    Phase B: out[n][c] = b[c] + sum_d rst[n][d] * W[c][d],
//             W streamed per k-chunk from L1 (low register pressure).
// ---------------------------------------------------------------------------
#define NPB 16   // nodes per block

__global__ __launch_bounds__(256)
void fused_acc_gemm_kernel(const float4* __restrict__ feat4,
                           const float4* __restrict__ W4,
                           const float* __restrict__ b,
                           float* __restrict__ out,
                           int n) {
    __shared__ float4 s_rst[NPB * (D_IN / 4)];   // 16 nodes * 16 float4 = 4KB

    int tid  = threadIdx.x;
    int wid  = tid >> 5;
    int lane = tid & 31;
    int half = lane >> 4;       // which node of this warp's pair
    int hl   = lane & 15;       // float4 index within the 64-float row
    int node0 = blockIdx.x * NPB;
    int lnode = wid * 2 + half;         // 0..15 local node
    int node  = node0 + lnode;

    // ---- Phase A: rst[node] = feat[node] + sum feat[esrc[j]] ----
    if (node < n) {
        float4 acc = __ldg(&feat4[(size_t)node * 16 + hl]);
        int j   = __ldg(&g_off[node]);
        int end = __ldg(&g_off[node + 1]);

        for (; j + 4 <= end; j += 4) {
            int s0 = __ldg(&g_esrc[j + 0]);
            int s1 = __ldg(&g_esrc[j + 1]);
            int s2 = __ldg(&g_esrc[j + 2]);
            int s3 = __ldg(&g_esrc[j + 3]);
            float4 v0 = __ldg(&feat4[(size_t)s0 * 16 + hl]);
            float4 v1 = __ldg(&feat4[(size_t)s1 * 16 + hl]);
            float4 v2 = __ldg(&feat4[(size_t)s2 * 16 + hl]);
            float4 v3 = __ldg(&feat4[(size_t)s3 * 16 + hl]);
            acc.x += (v0.x + v1.x) + (v2.x + v3.x);
            acc.y += (v0.y + v1.y) + (v2.y + v3.y);
            acc.z += (v0.z + v1.z) + (v2.z + v3.z);
            acc.w += (v0.w + v1.w) + (v2.w + v3.w);
        }
        for (; j < end; j++) {
            int s = __ldg(&g_esrc[j]);
            float4 v = __ldg(&feat4[(size_t)s * 16 + hl]);
            acc.x += v.x; acc.y += v.y; acc.z += v.z; acc.w += v.w;
        }
        s_rst[lnode * 16 + hl] = acc;
    }
    __syncthreads();

    // ---- Phase B: GEMM. thread -> (column, node-group of 8) ----
    int c  = tid & 127;              // output column
    int nb = (tid >> 7) * 8;         // local node base: 0 or 8

    float accs[8];
    float bias = __ldg(&b[c]);
    #pragma unroll
    for (int i = 0; i < 8; i++) accs[i] = bias;

    const float4* Wr = W4 + (size_t)c * 16;
    #pragma unroll
    for (int k = 0; k < 16; k++) {
        float4 w = __ldg(&Wr[k]);              // L1-resident after warmup
        #pragma unroll
        for (int i = 0; i < 8; i++) {
            float4 v = s_rst[(nb + i) * 16 + k];   // LDS.128 broadcast
            accs[i] += w.x * v.x + w.y * v.y + w.z * v.z + w.w * v.w;
        }
    }

    #pragma unroll
    for (int i = 0; i < 8; i++) {
        int node = node0 + nb + i;
        if (node < n) {
            out[(size_t)node * D_OUT + c] = accs[i];
        }
    }
}

// ---------------------------------------------------------------------------
// Inputs: feat [N*64] f32, radius [E] f32 (dead: weight = ones_like),
//         src [E] i32, dst [E] i32, W [128*64] f32, b [128] f32.
// Output: [N*128] f32.
// ---------------------------------------------------------------------------
extern "C" void kernel_launch(void* const* d_in, const int* in_sizes, int n_in,
                              void* d_out, int out_size) {
    const float* feat = (const float*)d_in[0];
    const int*   src  = (const int*)d_in[2];
    const int*   dst  = (const int*)d_in[3];
    const float* W    = (const float*)d_in[4];
    const float* b    = (const float*)d_in[5];
    float* out = (float*)d_out;

    int n = in_sizes[0] / D_IN;   // 100000
    int e = in_sizes[2];          // 1600000
    int nelem = n + 1;

    // CSR build (counting sort by dst)
    zero_cnt_kernel<<<(nelem + 255) / 256, 256>>>(nelem);
    hist_kernel<<<(e + 255) / 256, 256>>>(dst, e);
    int nsb = (nelem + SCAN_CHUNK - 1) / SCAN_CHUNK;
    scan1_kernel<<<nsb, 1024>>>(nelem);
    scan2_kernel<<<1, 32>>>(nsb);
    scan3_kernel<<<(nelem + 255) / 256, 256>>>(nelem);
    fill_kernel<<<(e + 255) / 256, 256>>>(src, dst, e);

    // Fused gather+reduce+GEMM
    fused_acc_gemm_kernel<<<(n + NPB - 1) / NPB, 256>>>(
        reinterpret_cast<const float4*>(feat),
        reinterpret_cast<const float4*>(W),
        b, out, n);
}

// round 5
// speedup vs baseline: 1.1416x; 1.1416x over previous
#include <cuda_runtime.h>
#include <stdint.h>

#define D_IN   64
#define D_OUT  128
#define MAX_NODES 100000
#define MAX_EDGES 1600000

#define SCAN_CHUNK 4096           // 1024 threads * 4 elems
#define SCAN_LOG2  12
#define SCAN_BLOCKS ((MAX_NODES + 1 + SCAN_CHUNK - 1) / SCAN_CHUNK)   // 25

// Scratch (device globals; no allocs allowed)
__device__ int   g_cnt[MAX_NODES + 1];
__device__ int   g_off[MAX_NODES + 1];   // per-block exclusive offsets (needs +bsum)
__device__ int   g_rank[MAX_EDGES];      // within-bucket rank from histogram
__device__ int   g_esrc[MAX_EDGES];      // src ids sorted by dst bucket
__device__ int   g_bsum[SCAN_BLOCKS];    // exclusive block sums
__device__ float g_rst[MAX_NODES * D_IN];

// ---------------------------------------------------------------------------
// 1) zero counts
// ---------------------------------------------------------------------------
__global__ void zero_cnt_kernel(int nelem) {
    int i = blockIdx.x * blockDim.x + threadIdx.x;
    if (i < nelem) g_cnt[i] = 0;
}

// ---------------------------------------------------------------------------
// 2) histogram of dst; atomicAdd return value = within-bucket rank (free)
// ---------------------------------------------------------------------------
__global__ void hist_kernel(const int* __restrict__ dst, int e) {
    int i = blockIdx.x * blockDim.x + threadIdx.x;
    if (i < e) {
        g_rank[i] = atomicAdd(&g_cnt[dst[i]], 1);
    }
}

// ---------------------------------------------------------------------------
// 3a) per-block exclusive scan (1024 threads x 4 elems)
// ---------------------------------------------------------------------------
__global__ __launch_bounds__(1024)
void scan1_kernel(int nelem) {
    __shared__ int s[1024];
    int t = threadIdx.x;
    int base = blockIdx.x * SCAN_CHUNK + t * 4;

    int v0 = (base + 0 < nelem) ? g_cnt[base + 0] : 0;
    int v1 = (base + 1 < nelem) ? g_cnt[base + 1] : 0;
    int v2 = (base + 2 < nelem) ? g_cnt[base + 2] : 0;
    int v3 = (base + 3 < nelem) ? g_cnt[base + 3] : 0;
    int tsum = v0 + v1 + v2 + v3;

    s[t] = tsum;
    __syncthreads();
    #pragma unroll
    for (int off = 1; off < 1024; off <<= 1) {
        int x = (t >= off) ? s[t - off] : 0;
        __syncthreads();
        if (t >= off) s[t] += x;
        __syncthreads();
    }
    int excl = s[t] - tsum;
    if (t == 1023) g_bsum[blockIdx.x] = s[1023];

    int run = excl;
    if (base + 0 < nelem) { g_off[base + 0] = run; } run += v0;
    if (base + 1 < nelem) { g_off[base + 1] = run; } run += v1;
    if (base + 2 < nelem) { g_off[base + 2] = run; } run += v2;
    if (base + 3 < nelem) { g_off[base + 3] = run; }
}

// 3b) exclusive scan of block sums — single-warp shfl scan (nblocks<=32)
__global__ void scan2_kernel(int nblocks) {
    int lane = threadIdx.x;
    int v = (lane < nblocks) ? g_bsum[lane] : 0;
    int orig = v;
    #pragma unroll
    for (int off = 1; off < 32; off <<= 1) {
        int x = __shfl_up_sync(0xFFFFFFFFu, v, off);
        if (lane >= off) v += x;
    }
    if (lane < nblocks) g_bsum[lane] = v - orig;   // exclusive
}

// final offset of element i = g_off[i] + g_bsum[i >> SCAN_LOG2]
__device__ __forceinline__ int final_off(int i) {
    return __ldg(&g_off[i]) + __ldg(&g_bsum[i >> SCAN_LOG2]);
}

// ---------------------------------------------------------------------------
// 4) fill sorted src list — no atomics, offsets finalized on the fly
// ---------------------------------------------------------------------------
__global__ void fill_kernel(const int* __restrict__ src,
                            const int* __restrict__ dst, int e) {
    int i = blockIdx.x * blockDim.x + threadIdx.x;
    if (i < e) {
        int d = dst[i];
        int p = final_off(d) + g_rank[i];
        g_esrc[p] = src[i];
    }
}

// ---------------------------------------------------------------------------
// 5) segment reduce: warp per node, lane owns float2 of the 64-dim row.
//    8-deep unroll, two independent accumulator chains (proven R3 version).
// ---------------------------------------------------------------------------
__global__ __launch_bounds__(256)
void accumulate_kernel(const float2* __restrict__ feat2, int n) {
    int warp = (blockIdx.x * blockDim.x + threadIdx.x) >> 5;
    int lane = threadIdx.x & 31;
    if (warp >= n) return;

    int node = warp;
    float2 acc0 = feat2[(size_t)node * 32 + lane];
    float2 acc1 = make_float2(0.f, 0.f);

    int j   = final_off(node);
    int end = final_off(node + 1);

    for (; j + 8 <= end; j += 8) {
        int s0 = __ldg(&g_esrc[j + 0]);
        int s1 = __ldg(&g_esrc[j + 1]);
        int s2 = __ldg(&g_esrc[j + 2]);
        int s3 = __ldg(&g_esrc[j + 3]);
        int s4 = __ldg(&g_esrc[j + 4]);
        int s5 = __ldg(&g_esrc[j + 5]);
        int s6 = __ldg(&g_esrc[j + 6]);
        int s7 = __ldg(&g_esrc[j + 7]);
        float2 v0 = feat2[(size_t)s0 * 32 + lane];
        float2 v1 = feat2[(size_t)s1 * 32 + lane];
        float2 v2 = feat2[(size_t)s2 * 32 + lane];
        float2 v3 = feat2[(size_t)s3 * 32 + lane];
        float2 v4 = feat2[(size_t)s4 * 32 + lane];
        float2 v5 = feat2[(size_t)s5 * 32 + lane];
        float2 v6 = feat2[(size_t)s6 * 32 + lane];
        float2 v7 = feat2[(size_t)s7 * 32 + lane];
        acc0.x += (v0.x + v1.x) + (v2.x + v3.x);
        acc0.y += (v0.y + v1.y) + (v2.y + v3.y);
        acc1.x += (v4.x + v5.x) + (v6.x + v7.x);
        acc1.y += (v4.y + v5.y) + (v6.y + v7.y);
    }
    for (; j + 2 <= end; j += 2) {
        int s0 = __ldg(&g_esrc[j + 0]);
        int s1 = __ldg(&g_esrc[j + 1]);
        float2 v0 = feat2[(size_t)s0 * 32 + lane];
        float2 v1 = feat2[(size_t)s1 * 32 + lane];
        acc0.x += v0.x; acc0.y += v0.y;
        acc1.x += v1.x; acc1.y += v1.y;
    }
    if (j < end) {
        int s = __ldg(&g_esrc[j]);
        float2 v = feat2[(size_t)s * 32 + lane];
        acc0.x += v.x; acc0.y += v.y;
    }

    float2 outv = make_float2(acc0.x + acc1.x, acc0.y + acc1.y);
    reinterpret_cast<float2*>(g_rst)[(size_t)node * 32 + lane] = outv;
}

// ---------------------------------------------------------------------------
// 6) out[n][o] = b[o] + sum_d rst[n][d] * W[o][d]   (proven R3 version)
// ---------------------------------------------------------------------------
#define NODES_PER_BLOCK 16

__global__ __launch_bounds__(D_OUT, 4)
void gemm_out_kernel(const float* __restrict__ W,
                     const float* __restrict__ b,
                     float* __restrict__ out,
                     int n) {
    __shared__ float4 s_rst4[NODES_PER_BLOCK * (D_IN / 4)];

    int t = threadIdx.x;          // output column 0..127
    int node0 = blockIdx.x * NODES_PER_BLOCK;

    #pragma unroll
    for (int r = 0; r < 2; r++) {
        int idx = t + r * D_OUT;           // 0..255
        int node = node0 + (idx >> 4);
        float4 v = make_float4(0.f, 0.f, 0.f, 0.f);
        if (node < n) {
            v = reinterpret_cast<const float4*>(g_rst)[(size_t)node * 16 + (idx & 15)];
        }
        s_rst4[idx] = v;
    }
    __syncthreads();

    float4 w[D_IN / 4];
    const float4* Wrow4 = reinterpret_cast<const float4*>(W + (size_t)t * D_IN);
    #pragma unroll
    for (int k = 0; k < D_IN / 4; k++) {
        w[k] = __ldg(&Wrow4[k]);
    }
    float bias = __ldg(&b[t]);

    #pragma unroll
    for (int i = 0; i < NODES_PER_BLOCK; i++) {
        int node = node0 + i;
        if (node >= n) break;
        float acc = bias;
        const float4* r4 = &s_rst4[i * (D_IN / 4)];
        #pragma unroll
        for (int k = 0; k < D_IN / 4; k++) {
            float4 v = r4[k];
            acc += v.x * w[k].x + v.y * w[k].y + v.z * w[k].z + v.w * w[k].w;
        }
        out[(size_t)node * D_OUT + t] = acc;
    }
}

// ---------------------------------------------------------------------------
// Inputs: feat [N*64] f32, radius [E] f32 (dead: weight = ones_like),
//         src [E] i32, dst [E] i32, W [128*64] f32, b [128] f32.
// Output: [N*128] f32.
// ---------------------------------------------------------------------------
extern "C" void kernel_launch(void* const* d_in, const int* in_sizes, int n_in,
                              void* d_out, int out_size) {
    const float* feat = (const float*)d_in[0];
    const int*   src  = (const int*)d_in[2];
    const int*   dst  = (const int*)d_in[3];
    const float* W    = (const float*)d_in[4];
    const float* b    = (const float*)d_in[5];
    float* out = (float*)d_out;

    int n = in_sizes[0] / D_IN;   // 100000
    int e = in_sizes[2];          // 1600000
    int nelem = n + 1;

    // CSR build (counting sort by dst) — no scan3, offsets finalized on read
    zero_cnt_kernel<<<(nelem + 255) / 256, 256>>>(nelem);
    hist_kernel<<<(e + 255) / 256, 256>>>(dst, e);
    int nsb = (nelem + SCAN_CHUNK - 1) / SCAN_CHUNK;
    scan1_kernel<<<nsb, 1024>>>(nelem);
    scan2_kernel<<<1, 32>>>(nsb);
    fill_kernel<<<(e + 255) / 256, 256>>>(src, dst, e);

    // Segment reduce: warp per node
    {
        int warps_per_block = 256 / 32;
        int blocks = (n + warps_per_block - 1) / warps_per_block;
        accumulate_kernel<<<blocks, 256>>>(
            reinterpret_cast<const float2*>(feat), n);
    }

    // out = rst @ W^T + b
    gemm_out_kernel<<<(n + NODES_PER_BLOCK - 1) / NODES_PER_BLOCK, D_OUT>>>(
        W, b, out, n);
}

// round 8
// speedup vs baseline: 1.1659x; 1.0213x over previous
#include <cuda_runtime.h>
#include <stdint.h>

#define D_IN   64
#define D_OUT  128
#define MAX_NODES 100000
#define MAX_EDGES 1600000

#define SCAN_CHUNK 4096           // 1024 threads * 4 elems
#define SCAN_LOG2  12
#define SCAN_BLOCKS ((MAX_NODES + 1 + SCAN_CHUNK - 1) / SCAN_CHUNK)   // 25

// Scratch (device globals; zero-initialized at module load; no allocs allowed)
__device__ int   g_cnt[MAX_NODES + 1];   // per-dst counts (zero at every entry)
__device__ int   g_off[MAX_NODES + 1];   // per-block exclusive offsets
__device__ int   g_rank[MAX_EDGES];      // within-bucket rank from histogram
__device__ int   g_esrc[MAX_EDGES];      // src ids sorted by dst bucket
__device__ int   g_bsum[SCAN_BLOCKS];    // exclusive block sums
__device__ float g_rst[MAX_NODES * D_IN];

// ---------------------------------------------------------------------------
// 1) histogram of dst; atomicAdd return value = within-bucket rank (free).
//    g_cnt is zero at entry: BSS on first call, fill re-zeroes for next call.
// ---------------------------------------------------------------------------
__global__ void hist_kernel(const int* __restrict__ dst, int e) {
    int i = blockIdx.x * blockDim.x + threadIdx.x;
    if (i < e) {
        g_rank[i] = atomicAdd(&g_cnt[dst[i]], 1);
    }
}

// ---------------------------------------------------------------------------
// 2a) per-block exclusive scan (1024 threads x 4 elems)
// ---------------------------------------------------------------------------
__global__ __launch_bounds__(1024)
void scan1_kernel(int nelem) {
    __shared__ int s[1024];
    int t = threadIdx.x;
    int base = blockIdx.x * SCAN_CHUNK + t * 4;

    int v0 = (base + 0 < nelem) ? g_cnt[base + 0] : 0;
    int v1 = (base + 1 < nelem) ? g_cnt[base + 1] : 0;
    int v2 = (base + 2 < nelem) ? g_cnt[base + 2] : 0;
    int v3 = (base + 3 < nelem) ? g_cnt[base + 3] : 0;
    int tsum = v0 + v1 + v2 + v3;

    s[t] = tsum;
    __syncthreads();
    #pragma unroll
    for (int off = 1; off < 1024; off <<= 1) {
        int x = (t >= off) ? s[t - off] : 0;
        __syncthreads();
        if (t >= off) s[t] += x;
        __syncthreads();
    }
    int excl = s[t] - tsum;
    if (t == 1023) g_bsum[blockIdx.x] = s[1023];

    int run = excl;
    if (base + 0 < nelem) { g_off[base + 0] = run; } run += v0;
    if (base + 1 < nelem) { g_off[base + 1] = run; } run += v1;
    if (base + 2 < nelem) { g_off[base + 2] = run; } run += v2;
    if (base + 3 < nelem) { g_off[base + 3] = run; }
}

// 2b) exclusive scan of block sums — single-warp shfl scan (nblocks<=32)
__global__ void scan2_kernel(int nblocks) {
    int lane = threadIdx.x;
    int v = (lane < nblocks) ? g_bsum[lane] : 0;
    int orig = v;
    #pragma unroll
    for (int off = 1; off < 32; off <<= 1) {
        int x = __shfl_up_sync(0xFFFFFFFFu, v, off);
        if (lane >= off) v += x;
    }
    if (lane < nblocks) g_bsum[lane] = v - orig;   // exclusive
}

// final offset of element i = g_off[i] + g_bsum[i >> SCAN_LOG2]
__device__ __forceinline__ int final_off(int i) {
    return __ldg(&g_off[i]) + __ldg(&g_bsum[i >> SCAN_LOG2]);
}

// ---------------------------------------------------------------------------
// 3) fill sorted src list (no atomics) + re-zero g_cnt for the next call
// ---------------------------------------------------------------------------
__global__ void fill_kernel(const int* __restrict__ src,
                            const int* __restrict__ dst, int e, int nelem) {
    int i = blockIdx.x * blockDim.x + threadIdx.x;
    if (i < e) {
        int d = dst[i];
        int p = final_off(d) + g_rank[i];
        g_esrc[p] = src[i];
    }
    if (i < nelem) g_cnt[i] = 0;
}

// ---------------------------------------------------------------------------
// 4) segment reduce: HALF-WARP (16 lanes x float4) per node, warp covers 2
//    nodes. LDG.128 halves load-instruction count vs float2 warp-per-node.
//    4-deep unroll, two independent accumulator chains.
// ---------------------------------------------------------------------------
__global__ __launch_bounds__(256)
void accumulate_kernel(const float4* __restrict__ feat4, int n) {
    int gtid = blockIdx.x * blockDim.x + threadIdx.x;
    int node = gtid >> 4;          // 16 lanes per node
    int hl   = threadIdx.x & 15;   // float4 index within the 64-float row
    if (node >= n) return;

    float4 acc0 = __ldg(&feat4[(size_t)node * 16 + hl]);
    float4 acc1 = make_float4(0.f, 0.f, 0.f, 0.f);

    int j   = final_off(node);
    int end = final_off(node + 1);

    for (; j + 4 <= end; j += 4) {
        int s0 = __ldg(&g_esrc[j + 0]);
        int s1 = __ldg(&g_esrc[j + 1]);
        int s2 = __ldg(&g_esrc[j + 2]);
        int s3 = __ldg(&g_esrc[j + 3]);
        float4 v0 = __ldg(&feat4[(size_t)s0 * 16 + hl]);
        float4 v1 = __ldg(&feat4[(size_t)s1 * 16 + hl]);
        float4 v2 = __ldg(&feat4[(size_t)s2 * 16 + hl]);
        float4 v3 = __ldg(&feat4[(size_t)s3 * 16 + hl]);
        acc0.x += v0.x + v1.x;  acc1.x += v2.x + v3.x;
        acc0.y += v0.y + v1.y;  acc1.y += v2.y + v3.y;
        acc0.z += v0.z + v1.z;  acc1.z += v2.z + v3.z;
        acc0.w += v0.w + v1.w;  acc1.w += v2.w + v3.w;
    }
    for (; j < end; j++) {
        int s = __ldg(&g_esrc[j]);
        float4 v = __ldg(&feat4[(size_t)s * 16 + hl]);
        acc0.x += v.x; acc0.y += v.y; acc0.z += v.z; acc0.w += v.w;
    }

    float4 outv = make_float4(acc0.x + acc1.x, acc0.y + acc1.y,
                              acc0.z + acc1.z, acc0.w + acc1.w);
    reinterpret_cast<float4*>(g_rst)[(size_t)node * 16 + hl] = outv;
}

// ---------------------------------------------------------------------------
// 5) out[n][o] = b[o] + sum_d rst[n][d] * W[o][d]   (proven R3/R5 version)
// ---------------------------------------------------------------------------
#define NODES_PER_BLOCK 16

__global__ __launch_bounds__(D_OUT, 4)
void gemm_out_kernel(const float* __restrict__ W,
                     const float* __restrict__ b,
                     float* __restrict__ out,
                     int n) {
    __shared__ float4 s_rst4[NODES_PER_BLOCK * (D_IN / 4)];

    int t = threadIdx.x;          // output column 0..127
    int node0 = blockIdx.x * NODES_PER_BLOCK;

    #pragma unroll
    for (int r = 0; r < 2; r++) {
        int idx = t + r * D_OUT;           // 0..255
        int node = node0 + (idx >> 4);
        float4 v = make_float4(0.f, 0.f, 0.f, 0.f);
        if (node < n) {
            v = reinterpret_cast<const float4*>(g_rst)[(size_t)node * 16 + (idx & 15)];
        }
        s_rst4[idx] = v;
    }
    __syncthreads();

    float4 w[D_IN / 4];
    const float4* Wrow4 = reinterpret_cast<const float4*>(W + (size_t)t * D_IN);
    #pragma unroll
    for (int k = 0; k < D_IN / 4; k++) {
        w[k] = __ldg(&Wrow4[k]);
    }
    float bias = __ldg(&b[t]);

    #pragma unroll
    for (int i = 0; i < NODES_PER_BLOCK; i++) {
        int node = node0 + i;
        if (node >= n) break;
        float acc = bias;
        const float4* r4 = &s_rst4[i * (D_IN / 4)];
        #pragma unroll
        for (int k = 0; k < D_IN / 4; k++) {
            float4 v = r4[k];
            acc += v.x * w[k].x + v.y * w[k].y + v.z * w[k].z + v.w * w[k].w;
        }
        out[(size_t)node * D_OUT + t] = acc;
    }
}

// ---------------------------------------------------------------------------
// Inputs: feat [N*64] f32, radius [E] f32 (dead: weight = ones_like),
//         src [E] i32, dst [E] i32, W [128*64] f32, b [128] f32.
// Output: [N*128] f32.
// ---------------------------------------------------------------------------
extern "C" void kernel_launch(void* const* d_in, const int* in_sizes, int n_in,
                              void* d_out, int out_size) {
    const float* feat = (const float*)d_in[0];
    const int*   src  = (const int*)d_in[2];
    const int*   dst  = (const int*)d_in[3];
    const float* W    = (const float*)d_in[4];
    const float* b    = (const float*)d_in[5];
    float* out = (float*)d_out;

    int n = in_sizes[0] / D_IN;   // 100000
    int e = in_sizes[2];          // 1600000
    int nelem = n + 1;

    // CSR build: hist -> scan1 -> scan2 -> fill (fill re-zeroes g_cnt)
    hist_kernel<<<(e + 255) / 256, 256>>>(dst, e);
    int nsb = (nelem + SCAN_CHUNK - 1) / SCAN_CHUNK;
    scan1_kernel<<<nsb, 1024>>>(nelem);
    scan2_kernel<<<1, 32>>>(nsb);
    fill_kernel<<<(e + 255) / 256, 256>>>(src, dst, e, nelem);

    // Segment reduce: half-warp per node (16 nodes per 256-thread block)
    {
        int blocks = (n * 16 + 255) / 256;
        accumulate_kernel<<<blocks, 256>>>(
            reinterpret_cast<const float4*>(feat), n);
    }

    // out = rst @ W^T + b
    gemm_out_kernel<<<(n + NODES_PER_BLOCK - 1) / NODES_PER_BLOCK, D_OUT>>>(
        W, b, out, n);
}